// round 2
// baseline (speedup 1.0000x reference)
#include <cuda_runtime.h>
#include <cstdint>

#define BB    2048
#define TSEQ  512
#define HH    51
#define TTOT  544      // TSEQ + 32 future
#define EPC   16       // batch elements per CTA
#define NCTA  128      // EPC * NCTA == BB
#define NTHR  128      // 64 j-lanes x 2 groups
#define MPT   8        // elements per thread
#define WROW  212      // floats per j-row (208 used; 212 => conflict-free LDS.128)
#define HROW  56       // floats per element row in h arrays (52 used, float4 aligned)

#define W_SZ   (51 * WROW)      // 10812 floats per weight matrix
#define XS_SZ  (EPC * TSEQ)     // 8192
#define HD_SZ  (EPC * HROW)     // 896
#define SM_FLOATS (3*W_SZ + XS_SZ + 2*HD_SZ + 256 + 256 + 256 + 64 + 16)
#define SM_BYTES  (SM_FLOATS * 4)

// ---------------- packed f32x2 helpers ----------------
__device__ __forceinline__ unsigned long long ffma2(unsigned long long a,
                                                    unsigned long long b,
                                                    unsigned long long c) {
    unsigned long long d;
    asm("fma.rn.f32x2 %0, %1, %2, %3;" : "=l"(d) : "l"(a), "l"(b), "l"(c));
    return d;
}
__device__ __forceinline__ unsigned long long pack2(float lo, float hi) {
    unsigned long long d;
    asm("mov.b64 %0, {%1, %2};" : "=l"(d) : "f"(lo), "f"(hi));
    return d;
}
__device__ __forceinline__ float2 unpack2(unsigned long long v) {
    float2 r;
    asm("mov.b64 {%0, %1}, %2;" : "=f"(r.x), "=f"(r.y) : "l"(v));
    return r;
}
// fast, accurate-enough (rel err ~1e-6) activations
__device__ __forceinline__ float sigf(float x) {
    return __fdividef(1.0f, 1.0f + __expf(-x));
}
__device__ __forceinline__ float tanhf_fast(float x) {
    return __fdividef(2.0f, 1.0f + __expf(-2.0f * x)) - 1.0f;
}

// z(4 gates, MPT elems) += W[j,:,:] . h[e,:]  -- k-paired f32x2:
// acc.{x,y} hold even-k / odd-k partial sums; z = acc.x + acc.y at the end.
__device__ __forceinline__ void matvec_acc(const float* __restrict__ Wrow,
                                           const float* __restrict__ hbase,
                                           unsigned long long aI[MPT],
                                           unsigned long long aF[MPT],
                                           unsigned long long aG[MPT],
                                           unsigned long long aO[MPT]) {
#pragma unroll
    for (int q = 0; q < 13; q++) {          // q covers k = 4q .. 4q+3
        ulonglong2 w01 = *(const ulonglong2*)(Wrow + q * 16);      // {wi,wf} @ k-pair0
        ulonglong2 w23 = *(const ulonglong2*)(Wrow + q * 16 + 4);  // {wg,wo} @ k-pair0
        ulonglong2 w45 = *(const ulonglong2*)(Wrow + q * 16 + 8);  // {wi,wf} @ k-pair1
        ulonglong2 w67 = *(const ulonglong2*)(Wrow + q * 16 + 12); // {wg,wo} @ k-pair1
#pragma unroll
        for (int m = 0; m < MPT; m++) {
            ulonglong2 hp = *(const ulonglong2*)(hbase + m * HROW + q * 4); // {h01,h23}
            aI[m] = ffma2(w01.x, hp.x, aI[m]);
            aF[m] = ffma2(w01.y, hp.x, aF[m]);
            aG[m] = ffma2(w23.x, hp.x, aG[m]);
            aO[m] = ffma2(w23.y, hp.x, aO[m]);
            aI[m] = ffma2(w45.x, hp.y, aI[m]);
            aF[m] = ffma2(w45.y, hp.y, aF[m]);
            aG[m] = ffma2(w67.x, hp.y, aG[m]);
            aO[m] = ffma2(w67.y, hp.y, aO[m]);
        }
    }
}

__global__ void __launch_bounds__(NTHR, 1)
lstm_seq_kernel(const float* __restrict__ input,
                const float* __restrict__ Wih1, const float* __restrict__ Whh1,
                const float* __restrict__ bih1, const float* __restrict__ bhh1,
                const float* __restrict__ Wih2, const float* __restrict__ Whh2,
                const float* __restrict__ bih2, const float* __restrict__ bhh2,
                const float* __restrict__ Wlin, const float* __restrict__ blin,
                float* __restrict__ out) {
    extern __shared__ float sm[];
    float* W1    = sm;                 // [51][26 kb][{i,f,g,o} x k-pair]
    float* W2i   = W1  + W_SZ;
    float* W2h   = W2i + W_SZ;
    float* xs    = W2h + W_SZ;         // [16][512]
    float* hd1   = xs  + XS_SZ;        // [16][56] plain h1
    float* hd2   = hd1 + HD_SZ;        // [16][56] plain h2
    float* wih1q = hd2 + HD_SZ;        // [64][4]
    float* b1q   = wih1q + 256;        // [64][4]
    float* b2q   = b1q   + 256;        // [64][4]
    float* wlin  = b2q   + 256;        // [64]
    float* outb  = wlin  + 64;         // [16]

    const int tid = threadIdx.x;
    const int g   = tid >> 6;          // group 0..1 (8 elements each)
    const int j   = tid & 63;          // hidden unit lane, active if < 51
    const int jj  = (j < HH) ? j : (HH - 1);   // clamped for safe smem reads
    const int b0  = blockIdx.x * EPC;
    const int e0  = g * MPT;

    // ---------- one-time init: rearrange weights (k-paired), stage inputs ----------
    for (int idx = tid; idx < 51 * 26; idx += NTHR) {
        int jr = idx / 26;
        int kb = idx - jr * 26;
#pragma unroll
        for (int gg = 0; gg < 4; gg++) {
#pragma unroll
            for (int s = 0; s < 2; s++) {
                int k = 2 * kb + s;
                int r = gg * 51 + jr;
                bool ok = (k < HH);
                float v1 = ok ? Whh1[r * 51 + k] : 0.f;
                float v2 = ok ? Wih2[r * 51 + k] : 0.f;
                float v3 = ok ? Whh2[r * 51 + k] : 0.f;
                int o = jr * WROW + kb * 8 + gg * 2 + s;
                W1 [o] = v1;
                W2i[o] = v2;
                W2h[o] = v3;
            }
        }
    }
    if (tid < 64) {
#pragma unroll
        for (int gg = 0; gg < 4; gg++) {
            bool ok = tid < HH;
            wih1q[tid * 4 + gg] = ok ? Wih1[gg * 51 + tid] : 0.f;
            b1q  [tid * 4 + gg] = ok ? (bih1[gg * 51 + tid] + bhh1[gg * 51 + tid]) : 0.f;
            b2q  [tid * 4 + gg] = ok ? (bih2[gg * 51 + tid] + bhh2[gg * 51 + tid]) : 0.f;
        }
        wlin[tid] = (tid < HH) ? Wlin[tid] : 0.f;
    }
    for (int idx = tid; idx < XS_SZ; idx += NTHR) {
        int e = idx >> 9, tc = idx & 511;
        xs[idx] = input[(size_t)(b0 + e) * TSEQ + tc];
    }
    for (int idx = tid; idx < HD_SZ; idx += NTHR) { hd1[idx] = 0.f; hd2[idx] = 0.f; }
    const float blin_r = blin[0];
    __syncthreads();

    float c1[MPT], c2[MPT];
#pragma unroll
    for (int m = 0; m < MPT; m++) { c1[m] = 0.f; c2[m] = 0.f; }

    const float*  W1r  = W1  + jj * WROW;
    const float*  W2ir = W2i + jj * WROW;
    const float*  W2hr = W2h + jj * WROW;
    const float4  wx   = *(const float4*)(wih1q + jj * 4);
    const float4  bq1  = *(const float4*)(b1q   + jj * 4);
    const float4  bq2  = *(const float4*)(b2q   + jj * 4);
    const float   wl   = (j < HH) ? wlin[j] : 0.f;
    const float*  hd1g = hd1 + e0 * HROW;
    const float*  hd2g = hd2 + e0 * HROW;

    // ---------- sequential scan: T teacher-forced + 32 feedback steps ----------
    for (int t = 0; t < TTOT; t++) {
        float xm[MPT];
        if (t < TSEQ) {
#pragma unroll
            for (int m = 0; m < MPT; m++) xm[m] = xs[(e0 + m) * TSEQ + t];
        } else {
#pragma unroll
            for (int m = 0; m < MPT; m++) xm[m] = outb[e0 + m];   // out[t-1]
        }

        // ---- layer 1 ----
        unsigned long long aI[MPT], aF[MPT], aG[MPT], aO[MPT];
#pragma unroll
        for (int m = 0; m < MPT; m++) {
            aI[m] = pack2(fmaf(wx.x, xm[m], bq1.x), 0.f);
            aF[m] = pack2(fmaf(wx.y, xm[m], bq1.y), 0.f);
            aG[m] = pack2(fmaf(wx.z, xm[m], bq1.z), 0.f);
            aO[m] = pack2(fmaf(wx.w, xm[m], bq1.w), 0.f);
        }
        matvec_acc(W1r, hd1g, aI, aF, aG, aO);

        float h1n[MPT];
#pragma unroll
        for (int m = 0; m < MPT; m++) {
            float2 vi = unpack2(aI[m]); float2 vf = unpack2(aF[m]);
            float2 vg = unpack2(aG[m]); float2 vo = unpack2(aO[m]);
            float ig = sigf(vi.x + vi.y);
            float fg = sigf(vf.x + vf.y);
            float gg = tanhf_fast(vg.x + vg.y);
            float og = sigf(vo.x + vo.y);
            c1[m]  = fg * c1[m] + ig * gg;
            h1n[m] = og * tanhf_fast(c1[m]);
        }
        __syncthreads();                                  // S1: old hd1 / outb reads done
        if (j < HH) {
#pragma unroll
            for (int m = 0; m < MPT; m++)
                hd1[(e0 + m) * HROW + j] = h1n[m];
        }
        if (tid < EPC) outb[tid] = blin_r;                // re-init this step's output
        __syncthreads();                                  // S2: new hd1 visible

        // ---- layer 2 ----
#pragma unroll
        for (int m = 0; m < MPT; m++) {
            aI[m] = pack2(bq2.x, 0.f);
            aF[m] = pack2(bq2.y, 0.f);
            aG[m] = pack2(bq2.z, 0.f);
            aO[m] = pack2(bq2.w, 0.f);
        }
        matvec_acc(W2ir, hd1g, aI, aF, aG, aO);   // W_ih2 @ h1(new)
        matvec_acc(W2hr, hd2g, aI, aF, aG, aO);   // W_hh2 @ h2(old)

        float h2n[MPT];
#pragma unroll
        for (int m = 0; m < MPT; m++) {
            float2 vi = unpack2(aI[m]); float2 vf = unpack2(aF[m]);
            float2 vg = unpack2(aG[m]); float2 vo = unpack2(aO[m]);
            float ig = sigf(vi.x + vi.y);
            float fg = sigf(vf.x + vf.y);
            float gg = tanhf_fast(vg.x + vg.y);
            float og = sigf(vo.x + vo.y);
            c2[m]  = fg * c2[m] + ig * gg;
            h2n[m] = og * tanhf_fast(c2[m]);
        }
        __syncthreads();                                  // S3: old hd2 reads done
        if (j < HH) {
#pragma unroll
            for (int m = 0; m < MPT; m++)
                hd2[(e0 + m) * HROW + j] = h2n[m];
        }
        // out[e] = sum_j wlin[j]*h2[j] + blin : warp butterfly + shared atomic
#pragma unroll
        for (int m = 0; m < MPT; m++) {
            float p = wl * h2n[m];
#pragma unroll
            for (int off = 16; off > 0; off >>= 1)
                p += __shfl_xor_sync(0xffffffffu, p, off);
            if ((tid & 31) == 0) atomicAdd(&outb[e0 + m], p);
        }
        __syncthreads();                                  // S4: outb + hd2 complete
        if (tid < EPC)
            out[(size_t)(b0 + tid) * TTOT + t] = outb[tid];
    }
}

extern "C" void kernel_launch(void* const* d_in, const int* in_sizes, int n_in,
                              void* d_out, int out_size) {
    const float* input = (const float*)d_in[0];
    const float* Wih1  = (const float*)d_in[1];
    const float* Whh1  = (const float*)d_in[2];
    const float* bih1  = (const float*)d_in[3];
    const float* bhh1  = (const float*)d_in[4];
    const float* Wih2  = (const float*)d_in[5];
    const float* Whh2  = (const float*)d_in[6];
    const float* bih2  = (const float*)d_in[7];
    const float* bhh2  = (const float*)d_in[8];
    const float* Wlin  = (const float*)d_in[9];
    const float* blin  = (const float*)d_in[10];
    // d_in[11] = "future" (=32), baked in as a constant.

    cudaFuncSetAttribute(lstm_seq_kernel,
                         cudaFuncAttributeMaxDynamicSharedMemorySize, SM_BYTES);
    lstm_seq_kernel<<<NCTA, NTHR, SM_BYTES>>>(input, Wih1, Whh1, bih1, bhh1,
                                              Wih2, Whh2, bih2, bhh2,
                                              Wlin, blin, (float*)d_out);
}

// round 3
// speedup vs baseline: 1.1764x; 1.1764x over previous
#include <cuda_runtime.h>
#include <cstdint>

#define BB    2048
#define TSEQ  512
#define HH    51
#define TTOT  544      // TSEQ + 32 future
#define EPC   16       // batch elements per CTA
#define NCTA  128      // EPC * NCTA == BB
#define NTHR  256      // 2 groups x 64 j x 2 gate-split
#define MPT   8        // elements per thread
#define WROW  232      // floats per j-row (208 used; 232 % 32 == 8 => conflict-free)
#define HROW  56       // floats per element row in h arrays (52 used, 16B aligned)

#define W_SZ   (51 * WROW)      // 11832 floats per weight matrix
#define XS_SZ  (EPC * TSEQ)     // 8192
#define HD_SZ  (EPC * HROW)     // 896
#define SM_FLOATS (3*W_SZ + XS_SZ + 2*HD_SZ + 256 + 256 + 256 + 64 + 16)
#define SM_BYTES  (SM_FLOATS * 4)

// ---------------- packed f32x2 helpers ----------------
__device__ __forceinline__ unsigned long long ffma2(unsigned long long a,
                                                    unsigned long long b,
                                                    unsigned long long c) {
    unsigned long long d;
    asm("fma.rn.f32x2 %0, %1, %2, %3;" : "=l"(d) : "l"(a), "l"(b), "l"(c));
    return d;
}
__device__ __forceinline__ unsigned long long pack2(float lo, float hi) {
    unsigned long long d;
    asm("mov.b64 %0, {%1, %2};" : "=l"(d) : "f"(lo), "f"(hi));
    return d;
}
__device__ __forceinline__ float2 unpack2(unsigned long long v) {
    float2 r;
    asm("mov.b64 {%0, %1}, %2;" : "=f"(r.x), "=f"(r.y) : "l"(v));
    return r;
}
__device__ __forceinline__ float sigf(float x) {
    return __fdividef(1.0f, 1.0f + __expf(-x));
}
__device__ __forceinline__ float tanhf_fast(float x) {
    return __fdividef(2.0f, 1.0f + __expf(-2.0f * x)) - 1.0f;
}

// acc{A,B}[m] += W[j, gates(2gs,2gs+1), :] . h[e0+m, :]   (k-paired f32x2)
__device__ __forceinline__ void matvec_acc(const float* __restrict__ Wrow,
                                           const float* __restrict__ hbase,
                                           unsigned long long aA[MPT],
                                           unsigned long long aB[MPT]) {
#pragma unroll
    for (int q = 0; q < 13; q++) {          // q covers k = 4q .. 4q+3
        // .x = {w[gA,k0],w[gA,k1]}, .y = {w[gB,k0],w[gB,k1]}
        ulonglong2 wa = *(const ulonglong2*)(Wrow + q * 16);      // k-pair {4q,4q+1}
        ulonglong2 wb = *(const ulonglong2*)(Wrow + q * 16 + 8);  // k-pair {4q+2,4q+3}
#pragma unroll
        for (int m = 0; m < MPT; m++) {
            ulonglong2 hp = *(const ulonglong2*)(hbase + m * HROW + q * 4);
            aA[m] = ffma2(wa.x, hp.x, aA[m]);
            aB[m] = ffma2(wa.y, hp.x, aB[m]);
            aA[m] = ffma2(wb.x, hp.y, aA[m]);
            aB[m] = ffma2(wb.y, hp.y, aB[m]);
        }
    }
}

__global__ void __launch_bounds__(NTHR, 1)
lstm_seq_kernel(const float* __restrict__ input,
                const float* __restrict__ Wih1, const float* __restrict__ Whh1,
                const float* __restrict__ bih1, const float* __restrict__ bhh1,
                const float* __restrict__ Wih2, const float* __restrict__ Whh2,
                const float* __restrict__ bih2, const float* __restrict__ bhh2,
                const float* __restrict__ Wlin, const float* __restrict__ blin,
                float* __restrict__ out) {
    extern __shared__ float sm[];
    float* W1    = sm;                 // [51][26 kb][4 gates][2 k]
    float* W2i   = W1  + W_SZ;
    float* W2h   = W2i + W_SZ;
    float* xs    = W2h + W_SZ;         // [16][512]
    float* hd1   = xs  + XS_SZ;        // [16][56]
    float* hd2   = hd1 + HD_SZ;        // [16][56]
    float* wih1q = hd2 + HD_SZ;        // [64][4]
    float* b1q   = wih1q + 256;        // [64][4]
    float* b2q   = b1q   + 256;        // [64][4]
    float* wlin  = b2q   + 256;        // [64]
    float* outb  = wlin  + 64;         // [16]

    const int tid = threadIdx.x;
    const int g   = tid >> 7;            // group 0..1 (8 elements each)
    const int r   = tid & 127;
    const int j   = r >> 1;              // hidden unit 0..63 (active < 51)
    const int gs  = r & 1;               // gate split: 0 -> (i,f), 1 -> (g,o)
    const int jj  = (j < HH) ? j : (HH - 1);
    const int b0  = blockIdx.x * EPC;
    const int e0  = g * MPT;

    // activation constants: a1 = kA / (1 + exp(kmul*z)) + kB
    // gs0: sigmoid (kmul=-1, kA=1, kB=0); gs1: tanh (kmul=-2, kA=2, kB=-1)
    const float kmul = gs ? -2.0f : -1.0f;
    const float kA   = gs ?  2.0f :  1.0f;
    const float kB   = gs ? -1.0f :  0.0f;

    // ---------- one-time init: rearrange weights (k-paired), stage inputs ----------
    for (int idx = tid; idx < 51 * 26; idx += NTHR) {
        int jr = idx / 26;
        int kb = idx - jr * 26;
#pragma unroll
        for (int gg = 0; gg < 4; gg++) {
#pragma unroll
            for (int s = 0; s < 2; s++) {
                int k = 2 * kb + s;
                int rr = gg * 51 + jr;
                bool ok = (k < HH);
                int o = jr * WROW + kb * 8 + gg * 2 + s;
                W1 [o] = ok ? Whh1[rr * 51 + k] : 0.f;
                W2i[o] = ok ? Wih2[rr * 51 + k] : 0.f;
                W2h[o] = ok ? Whh2[rr * 51 + k] : 0.f;
            }
        }
    }
    if (tid < 64) {
#pragma unroll
        for (int gg = 0; gg < 4; gg++) {
            bool ok = tid < HH;
            wih1q[tid * 4 + gg] = ok ? Wih1[gg * 51 + tid] : 0.f;
            b1q  [tid * 4 + gg] = ok ? (bih1[gg * 51 + tid] + bhh1[gg * 51 + tid]) : 0.f;
            b2q  [tid * 4 + gg] = ok ? (bih2[gg * 51 + tid] + bhh2[gg * 51 + tid]) : 0.f;
        }
        wlin[tid] = (tid < HH) ? Wlin[tid] : 0.f;
    }
    for (int idx = tid; idx < XS_SZ; idx += NTHR) {
        int e = idx >> 9, tc = idx & 511;
        xs[idx] = input[(size_t)(b0 + e) * TSEQ + tc];
    }
    for (int idx = tid; idx < HD_SZ; idx += NTHR) { hd1[idx] = 0.f; hd2[idx] = 0.f; }
    const float blin_r = blin[0];
    __syncthreads();

    float c1[MPT], c2[MPT];
#pragma unroll
    for (int m = 0; m < MPT; m++) { c1[m] = 0.f; c2[m] = 0.f; }

    const float*  W1r  = W1  + jj * WROW + gs * 4;
    const float*  W2ir = W2i + jj * WROW + gs * 4;
    const float*  W2hr = W2h + jj * WROW + gs * 4;
    const float2  wxp  = *(const float2*)(wih1q + jj * 4 + gs * 2); // my 2 gates
    const float2  bp1  = *(const float2*)(b1q   + jj * 4 + gs * 2);
    const float2  bp2  = *(const float2*)(b2q   + jj * 4 + gs * 2);
    const float   wl   = (gs == 0) ? wlin[j] : 0.f;   // wlin[j>=51]==0
    const float*  hd1g = hd1 + e0 * HROW;
    const float*  hd2g = hd2 + e0 * HROW;

    // ---------- sequential scan: T teacher-forced + 32 feedback steps ----------
    for (int t = 0; t < TTOT; t++) {
        float xm[MPT];
        if (t < TSEQ) {
#pragma unroll
            for (int m = 0; m < MPT; m++) xm[m] = xs[(e0 + m) * TSEQ + t];
        } else {
#pragma unroll
            for (int m = 0; m < MPT; m++) xm[m] = outb[e0 + m];   // out[t-1]
        }

        // ---- layer 1 ----
        unsigned long long aA[MPT], aB[MPT];
#pragma unroll
        for (int m = 0; m < MPT; m++) {
            aA[m] = pack2(fmaf(wxp.x, xm[m], bp1.x), 0.f);
            aB[m] = pack2(fmaf(wxp.y, xm[m], bp1.y), 0.f);
        }
        matvec_acc(W1r, hd1g, aA, aB);

        float h1n[MPT];
#pragma unroll
        for (int m = 0; m < MPT; m++) {
            float2 va = unpack2(aA[m]);
            float2 vb = unpack2(aB[m]);
            float za = va.x + va.y, zb = vb.x + vb.y;
            float a1 = kA * __fdividef(1.0f, 1.0f + __expf(kmul * za)) + kB; // ig | gg
            float a2 = sigf(zb);                                             // fg | og
            float g_r = __shfl_xor_sync(0xffffffffu, a1, 1);  // gs0 receives gg
            float o_r = __shfl_xor_sync(0xffffffffu, a2, 1);  // gs0 receives og
            c1[m]  = a2 * c1[m] + a1 * g_r;       // valid at gs0 only
            h1n[m] = o_r * tanhf_fast(c1[m]);     // valid at gs0 only
        }
        __syncthreads();                                  // S1: old hd1 / outb reads done
        if (gs == 0 && j < HH) {
#pragma unroll
            for (int m = 0; m < MPT; m++)
                hd1[(e0 + m) * HROW + j] = h1n[m];
        }
        if (tid < EPC) outb[tid] = blin_r;                // re-init this step's output
        __syncthreads();                                  // S2: new hd1 visible

        // ---- layer 2 ----
#pragma unroll
        for (int m = 0; m < MPT; m++) {
            aA[m] = pack2(bp2.x, 0.f);
            aB[m] = pack2(bp2.y, 0.f);
        }
        matvec_acc(W2ir, hd1g, aA, aB);   // W_ih2 @ h1(new)
        matvec_acc(W2hr, hd2g, aA, aB);   // W_hh2 @ h2(old)

        float h2n[MPT];
#pragma unroll
        for (int m = 0; m < MPT; m++) {
            float2 va = unpack2(aA[m]);
            float2 vb = unpack2(aB[m]);
            float za = va.x + va.y, zb = vb.x + vb.y;
            float a1 = kA * __fdividef(1.0f, 1.0f + __expf(kmul * za)) + kB;
            float a2 = sigf(zb);
            float g_r = __shfl_xor_sync(0xffffffffu, a1, 1);
            float o_r = __shfl_xor_sync(0xffffffffu, a2, 1);
            c2[m]  = a2 * c2[m] + a1 * g_r;
            h2n[m] = o_r * tanhf_fast(c2[m]);
        }
        __syncthreads();                                  // S3: old hd2 reads done
        if (gs == 0 && j < HH) {
#pragma unroll
            for (int m = 0; m < MPT; m++)
                hd2[(e0 + m) * HROW + j] = h2n[m];
        }
        // out[e] = sum_j wlin[j]*h2[j] + blin : warp butterfly (16 j per warp) + atomic
#pragma unroll
        for (int m = 0; m < MPT; m++) {
            float p = wl * h2n[m];                        // wl==0 at gs1 / j>=51
#pragma unroll
            for (int off = 16; off > 0; off >>= 1)
                p += __shfl_xor_sync(0xffffffffu, p, off);
            if ((tid & 31) == 0) atomicAdd(&outb[e0 + m], p);
        }
        __syncthreads();                                  // S4: outb + hd2 complete
        if (tid < EPC)
            out[(size_t)(b0 + tid) * TTOT + t] = outb[tid];
    }
}

extern "C" void kernel_launch(void* const* d_in, const int* in_sizes, int n_in,
                              void* d_out, int out_size) {
    const float* input = (const float*)d_in[0];
    const float* Wih1  = (const float*)d_in[1];
    const float* Whh1  = (const float*)d_in[2];
    const float* bih1  = (const float*)d_in[3];
    const float* bhh1  = (const float*)d_in[4];
    const float* Wih2  = (const float*)d_in[5];
    const float* Whh2  = (const float*)d_in[6];
    const float* bih2  = (const float*)d_in[7];
    const float* bhh2  = (const float*)d_in[8];
    const float* Wlin  = (const float*)d_in[9];
    const float* blin  = (const float*)d_in[10];
    // d_in[11] = "future" (=32), baked in as a constant.

    cudaFuncSetAttribute(lstm_seq_kernel,
                         cudaFuncAttributeMaxDynamicSharedMemorySize, SM_BYTES);
    lstm_seq_kernel<<<NCTA, NTHR, SM_BYTES>>>(input, Wih1, Whh1, bih1, bhh1,
                                              Wih2, Whh2, bih2, bhh2,
                                              Wlin, blin, (float*)d_out);
}